// round 7
// baseline (speedup 1.0000x reference)
#include <cuda_runtime.h>
#include <cuda_fp16.h>
#include <math.h>
#include <stdint.h>

// ---------------------------------------------------------------------------
// Problem constants
// ---------------------------------------------------------------------------
constexpr int B_  = 4096;    // batch
constexpr int G_  = 1024;    // gate width
constexpr int KD  = 2048;    // IN + g  (GEMM K — plain fp16 both sides)
constexpr int ND  = 5120;    // out_dim
constexpr long long OUT_OH = (long long)B_ * 4 * G_;

// ---------------------------------------------------------------------------
// Static scratch (no allocations allowed)
// ---------------------------------------------------------------------------
__device__ __align__(256) __half g_A [(size_t)B_ * KD];    // 16.8 MB
__device__ __align__(256) __half g_W1[(size_t)ND * KD];    // 21 MB
__device__ __align__(256) __half g_W2[(size_t)ND * KD];    // 21 MB
__device__ __align__(256) float  g_zg[(size_t)B_ * ND];    // 84 MB
__device__ double g_part[2 * 16384];

// ---------------------------------------------------------------------------
// PTX helpers (all baseline sm_80+ features)
// ---------------------------------------------------------------------------
__device__ __forceinline__ uint32_t smem_u32(const void* p) {
    uint32_t a;
    asm("{ .reg .u64 t; cvta.to.shared.u64 t, %1; cvt.u32.u64 %0, t; }" : "=r"(a) : "l"(p));
    return a;
}
__device__ __forceinline__ void cp_async16(uint32_t dst, const void* src) {
    asm volatile("cp.async.cg.shared.global [%0], [%1], 16;" :: "r"(dst), "l"(src) : "memory");
}
#define CP_COMMIT()  asm volatile("cp.async.commit_group;" ::: "memory")
#define CP_WAIT(n)   asm volatile("cp.async.wait_group %0;" :: "n"(n) : "memory")

#define LDSM4(r0, r1, r2, r3, addr) \
    asm volatile("ldmatrix.sync.aligned.m8n8.x4.shared.b16 {%0,%1,%2,%3}, [%4];" \
                 : "=r"(r0), "=r"(r1), "=r"(r2), "=r"(r3) : "r"(addr))

#define MMA16816(d, a, b0v, b1v) \
    asm volatile("mma.sync.aligned.m16n8k16.row.col.f32.f16.f16.f32 " \
                 "{%0,%1,%2,%3}, {%4,%5,%6,%7}, {%8,%9}, {%0,%1,%2,%3};" \
                 : "+f"((d)[0]), "+f"((d)[1]), "+f"((d)[2]), "+f"((d)[3]) \
                 : "r"((a)[0]), "r"((a)[1]), "r"((a)[2]), "r"((a)[3]), \
                   "r"(b0v), "r"(b1v))

#define SWZ(o) ((o) ^ (((o) >> 3) & 0x70))

__device__ __forceinline__ float sigm(float x) { return 1.0f / (1.0f + expf(-x)); }

// ---------------------------------------------------------------------------
// Pack A = fp16([input | h2_fl])
// ---------------------------------------------------------------------------
__global__ void prep_kernel(const float* __restrict__ inp,
                            const int*   __restrict__ hidden)
{
    int idx = blockIdx.x * 256 + threadIdx.x;      // 0 .. B_*KD-1
    int i = idx >> 11;
    int k = idx & 2047;
    float x = (k < 1024) ? inp[(size_t)i * 1024 + k]
                         : (float)hidden[(size_t)i * 4096 + k] * (1.0f / 8388608.0f);
    g_A[idx] = __float2half_rn(x);
}

// ---------------------------------------------------------------------------
// W1,W2 -> fp16 (one launch)
// ---------------------------------------------------------------------------
__global__ void wconv_kernel(const float* __restrict__ W1src,
                             const float* __restrict__ W2src)
{
    int idx = blockIdx.x * 256 + threadIdx.x;      // 0 .. 2*ND*KD-1
    constexpr int HALF = ND * KD;
    if (idx < HALF) g_W1[idx] = __float2half_rn(W1src[idx]);
    else            g_W2[idx - HALF] = __float2half_rn(W2src[idx - HALF]);
}

// ---------------------------------------------------------------------------
// mma.sync fp16 GEMM:  g_zg = A(B_ x 2048) @ W^T (ND x 2048) + bias
// CTA tile 128(M)x256(N), 8 warps, warp tile 64x64, K-chunk 64,
// SW128-swizzled smem, 3-stage cp.async pipeline (one barrier/chunk),
// double-buffered ldmatrix fragments.
// ---------------------------------------------------------------------------
constexpr int TM = 128, TN = 256, STAGES = 3;
constexpr int A_BYTES = TM * 128;                  // 16384 per stage
constexpr int STAGE_BYTES = A_BYTES + TN * 128;    // 49152
constexpr int SMEM_TOTAL = STAGES * STAGE_BYTES;   // 147456
constexpr int NCHUNK = KD / 64;                    // 32

__global__ __launch_bounds__(256, 1)
void gemm_kernel(int which, const float* __restrict__ bias)
{
    extern __shared__ char smem[];
    const uint32_t sb = smem_u32(smem);
    const int tid  = threadIdx.x;
    const int wid  = tid >> 5;
    const int lane = tid & 31;
    const int bm = blockIdx.y * TM;
    const int bn = blockIdx.x * TN;
    const __half* __restrict__ Ag = g_A;
    const __half* __restrict__ Wg = which ? g_W2 : g_W1;

    // ---- producer setup: 12 x 16B cp.async per thread per stage ----
    // A: rows (tid>>3) + 32*i (i=0..3); B: rows (tid>>3) + 32*j (j=0..7)
    const int prow = tid >> 3;
    const int pgrp = tid & 7;
    const char* Abase = (const char*)(Ag + (size_t)(bm + prow) * KD) + pgrp * 16;
    const char* Bbase = (const char*)(Wg + (size_t)(bn + prow) * KD) + pgrp * 16;
    const uint32_t dA = SWZ((uint32_t)(prow * 128 + pgrp * 16));  // +i*4096 rows (SWZ-safe: row step 32)
    constexpr size_t RSTRIDE = (size_t)32 * KD * 2;               // 131072 B

    // ---- consumer setup: ldmatrix lane addressing ----
    const int wm = (wid & 1) * 64;                 // warp M offset
    const int wn = (wid >> 1) * 64;                // warp N offset
    const int q  = lane >> 3;                      // quad 0..3
    const int l7 = lane & 7;

    uint32_t a_rt[4], a_xor[4];
#pragma unroll
    for (int mt = 0; mt < 4; mt++) {
        const int row = wm + mt * 16 + l7 + (q & 1) * 8;
        a_rt[mt]  = (uint32_t)row * 128;
        a_xor[mt] = (uint32_t)(row & 7) * 16;
    }
    const uint32_t a_kh = (uint32_t)(q >> 1) * 16;

    uint32_t b_rt[4], b_xor[4];
#pragma unroll
    for (int nb2 = 0; nb2 < 4; nb2++) {
        const int row = wn + nb2 * 16 + l7 + (q >> 1) * 8;
        b_rt[nb2]  = (uint32_t)(A_BYTES + row * 128);
        b_xor[nb2] = (uint32_t)(row & 7) * 16;
    }
    const uint32_t b_kh = (uint32_t)(q & 1) * 16;

    float acc[4][8][4];
#pragma unroll
    for (int mt = 0; mt < 4; mt++)
#pragma unroll
        for (int nb = 0; nb < 8; nb++)
#pragma unroll
            for (int r = 0; r < 4; r++) acc[mt][nb][r] = 0.0f;

    // ---- prologue: issue chunks 0,1 into stages 0,1 ----
#pragma unroll
    for (int s = 0; s < 2; s++) {
        const uint32_t sdst = sb + s * STAGE_BYTES;
        const size_t koff = (size_t)s * 128;
#pragma unroll
        for (int i = 0; i < 4; i++)
            cp_async16(sdst + dA + i * 4096, Abase + i * RSTRIDE + koff);
#pragma unroll
        for (int j = 0; j < 8; j++)
            cp_async16(sdst + A_BYTES + dA + j * 4096, Bbase + j * RSTRIDE + koff);
        CP_COMMIT();
    }

    uint32_t af[2][4][4];     // [buf][mt][reg]
    uint32_t bfr[2][4][4];    // [buf][nb2][reg]

    // ---- main loop: one barrier per chunk ----
    int sc = 0;   // compute stage
    int sl = 2;   // load stage
    for (int c = 0; c < NCHUNK; c++) {
        CP_WAIT(1);                                 // chunk c arrived (this thread)
        __syncthreads();                            // visible to all; stage sl free
        if (c + 2 < NCHUNK) {
            const uint32_t sdst = sb + sl * STAGE_BYTES;
            const size_t koff = (size_t)(c + 2) * 128;
#pragma unroll
            for (int i = 0; i < 4; i++)
                cp_async16(sdst + dA + i * 4096, Abase + i * RSTRIDE + koff);
#pragma unroll
            for (int j = 0; j < 8; j++)
                cp_async16(sdst + A_BYTES + dA + j * 4096, Bbase + j * RSTRIDE + koff);
        }
        CP_COMMIT();

        const uint32_t sA = sb + sc * STAGE_BYTES;

        // load fragments for kk=0
#pragma unroll
        for (int mt = 0; mt < 4; mt++)
            LDSM4(af[0][mt][0], af[0][mt][1], af[0][mt][2], af[0][mt][3],
                  sA + a_rt[mt] + (a_kh ^ a_xor[mt]));
#pragma unroll
        for (int nb2 = 0; nb2 < 4; nb2++)
            LDSM4(bfr[0][nb2][0], bfr[0][nb2][1], bfr[0][nb2][2], bfr[0][nb2][3],
                  sA + b_rt[nb2] + (b_kh ^ b_xor[nb2]));

#pragma unroll
        for (int kk = 0; kk < 4; kk++) {
            const int cur = kk & 1;
            if (kk < 3) {
                const int nxt = cur ^ 1;
                const uint32_t kb = (kk + 1) * 32;
#pragma unroll
                for (int mt = 0; mt < 4; mt++)
                    LDSM4(af[nxt][mt][0], af[nxt][mt][1], af[nxt][mt][2], af[nxt][mt][3],
                          sA + a_rt[mt] + ((kb + a_kh) ^ a_xor[mt]));
#pragma unroll
                for (int nb2 = 0; nb2 < 4; nb2++)
                    LDSM4(bfr[nxt][nb2][0], bfr[nxt][nb2][1], bfr[nxt][nb2][2], bfr[nxt][nb2][3],
                          sA + b_rt[nb2] + ((kb + b_kh) ^ b_xor[nb2]));
            }
#pragma unroll
            for (int mt = 0; mt < 4; mt++)
#pragma unroll
                for (int nb = 0; nb < 8; nb++)
                    MMA16816(acc[mt][nb], af[cur][mt],
                             bfr[cur][nb >> 1][(nb & 1) * 2],
                             bfr[cur][nb >> 1][(nb & 1) * 2 + 1]);
        }

        sc = (sc == 2) ? 0 : sc + 1;
        sl = (sl == 2) ? 0 : sl + 1;
    }

    // ---- epilogue: direct STG with bias (hoisted) ----
    const int trow = lane >> 2;
    const int tcol = (lane & 3) * 2;
    float bz0[8], bz1[8];
#pragma unroll
    for (int nb = 0; nb < 8; nb++) {
        const int gcol = bn + wn + nb * 8 + tcol;
        bz0[nb] = __ldg(bias + gcol);
        bz1[nb] = __ldg(bias + gcol + 1);
    }
#pragma unroll
    for (int mt = 0; mt < 4; mt++) {
        const int grow = bm + wm + mt * 16 + trow;
#pragma unroll
        for (int nb = 0; nb < 8; nb++) {
            const int gcol = bn + wn + nb * 8 + tcol;
            float2 v0, v1;
            v0.x = acc[mt][nb][0] + bz0[nb]; v0.y = acc[mt][nb][1] + bz1[nb];
            v1.x = acc[mt][nb][2] + bz0[nb]; v1.y = acc[mt][nb][3] + bz1[nb];
            *(float2*)(g_zg + (size_t)grow * ND + gcol)       = v0;
            *(float2*)(g_zg + (size_t)(grow + 8) * ND + gcol) = v1;
        }
    }
}

// ---------------------------------------------------------------------------
// Elementwise fixed-point half-step (same math as reference)
// ---------------------------------------------------------------------------
__global__ void elem_kernel(const int* __restrict__ hidden,
                            float* __restrict__ out,
                            int step)
{
    __shared__ double sred[256];
    const int tid = threadIdx.x;
    const int idx = blockIdx.x * 256 + tid;       // 0 .. B_*G_-1
    const int i = idx >> 10;
    const int j = idx & 1023;

    const float* zrow = g_zg + (size_t)i * ND + j;
    const float xz = zrow[0];
    const float xg = zrow[G_];
    const float xf = zrow[2 * G_];
    const float xo = zrow[3 * G_];
    const float xp = zrow[4 * G_];

    const float z  = 0.96875f * sigm(xz) + 0.03125f;
    const float gg = tanhf(xg);
    const float f  = sigm(xf);
    const float o  = sigm(xo);
    const float p  = 0.96875f * sigm(xp) + 0.03125f;

    int zi = (int)(z * 1024.0f); if (zi < 1) zi = 1;
    int pi = (int)(p * 1024.0f); if (pi < 1) pi = 1;

    const int* hrow = hidden + (size_t)i * (4 * G_);
    const int cv = hrow[(2 + step) * G_ + j];
    const int hv = hrow[step * G_ + j];

    const float fg = f * gg;
    const int cn = (int)(((long long)cv * (long long)zi) >> 10) + (int)(fg * 8388608.0f);
    const float cfl = (float)cn * (1.0f / 8388608.0f);
    const float ot = o * tanhf(cfl);
    const int hn = (int)(((long long)hv * (long long)pi) >> 10) + (int)(ot * 8388608.0f);

    const size_t ro = (size_t)i * (4 * G_);
    out[ro + (size_t)step * G_ + j]       = (float)hn;
    out[ro + (size_t)(2 + step) * G_ + j] = (float)cn;

    const float hfl = (float)hn * (1.0f / 8388608.0f);
    out[OUT_OH + (size_t)i * (2 * G_) + (size_t)step * G_ + j] = hfl;

    if (step == 0)
        g_A[(size_t)i * KD + 1024 + j] = __float2half_rn(hfl);

    sred[tid] = (double)(logf(z) + logf(p));
    __syncthreads();
#pragma unroll
    for (int s = 128; s > 0; s >>= 1) {
        if (tid < s) sred[tid] += sred[tid + s];
        __syncthreads();
    }
    if (tid == 0) g_part[step * 16384 + blockIdx.x] = sred[0];
}

__global__ void bits_kernel(float* __restrict__ out, long long last_idx)
{
    __shared__ double sred[1024];
    const int tid = threadIdx.x;
    double s = 0.0;
    for (int i = tid; i < 2 * 16384; i += 1024) s += g_part[i];
    sred[tid] = s;
    __syncthreads();
#pragma unroll
    for (int k = 512; k > 0; k >>= 1) {
        if (tid < k) sred[tid] += sred[tid + k];
        __syncthreads();
    }
    if (tid == 0)
        out[last_idx] = (float)(-sred[0] / 0.6931471805599453);
}

// ---------------------------------------------------------------------------
extern "C" void kernel_launch(void* const* d_in, const int* in_sizes, int n_in,
                              void* d_out, int out_size)
{
    const float* inp    = (const float*)d_in[0];   // (4096, 1024)
    const int*   hidden = (const int*)  d_in[1];   // (4096, 4096)
    const float* W1     = (const float*)d_in[2];   // (5120, 2048)
    const float* b1     = (const float*)d_in[3];
    const float* W2     = (const float*)d_in[4];
    const float* b2     = (const float*)d_in[5];
    float* out = (float*)d_out;

    static bool attr_set = false;
    if (!attr_set) {
        cudaFuncSetAttribute(gemm_kernel, cudaFuncAttributeMaxDynamicSharedMemorySize, SMEM_TOTAL);
        attr_set = true;
    }

    const int elem_blocks = (B_ * G_) / 256;        // 16384
    dim3 gemm_grid(ND / TN, B_ / TM);               // (20, 32)

    prep_kernel <<<(B_ * KD) / 256, 256>>>(inp, hidden);
    wconv_kernel<<<(2 * ND * KD) / 256, 256>>>(W1, W2);

    gemm_kernel<<<gemm_grid, 256, SMEM_TOTAL>>>(0, b1);
    elem_kernel<<<elem_blocks, 256>>>(hidden, out, 0);
    gemm_kernel<<<gemm_grid, 256, SMEM_TOTAL>>>(1, b2);
    elem_kernel<<<elem_blocks, 256>>>(hidden, out, 1);
    bits_kernel<<<1, 1024>>>(out, (long long)out_size - 1);
}

// round 9
// speedup vs baseline: 1.2233x; 1.2233x over previous
#include <cuda_runtime.h>
#include <cuda_fp16.h>
#include <math.h>
#include <stdint.h>

// ---------------------------------------------------------------------------
// Problem constants
// ---------------------------------------------------------------------------
constexpr int B_  = 4096;    // batch
constexpr int G_  = 1024;    // gate width
constexpr int KD  = 2048;    // IN + g  (GEMM K)
constexpr int ND  = 5120;    // out_dim
constexpr long long OUT_OH = (long long)B_ * 4 * G_;

// ---------------------------------------------------------------------------
// Static scratch (no allocations allowed)
// ---------------------------------------------------------------------------
__device__ __align__(256) __half g_A  [(size_t)B_ * KD];   // [input | h2_fl] 16.8 MB
__device__ __align__(256) __half g_Ah1[(size_t)B_ * G_];   // h1_fl (step-1 h half) 8.4 MB
__device__ __align__(256) __half g_W1[(size_t)ND * KD];    // 21 MB
__device__ __align__(256) __half g_W2[(size_t)ND * KD];    // 21 MB
__device__ double g_part[2 * 1024];

// ---------------------------------------------------------------------------
// PTX helpers (all baseline sm_80+ features)
// ---------------------------------------------------------------------------
__device__ __forceinline__ uint32_t smem_u32(const void* p) {
    uint32_t a;
    asm("{ .reg .u64 t; cvta.to.shared.u64 t, %1; cvt.u32.u64 %0, t; }" : "=r"(a) : "l"(p));
    return a;
}
__device__ __forceinline__ void cp_async16(uint32_t dst, const void* src) {
    asm volatile("cp.async.cg.shared.global [%0], [%1], 16;" :: "r"(dst), "l"(src) : "memory");
}
#define CP_COMMIT()  asm volatile("cp.async.commit_group;" ::: "memory")
#define CP_WAIT(n)   asm volatile("cp.async.wait_group %0;" :: "n"(n) : "memory")

#define LDSM4(r0, r1, r2, r3, addr) \
    asm volatile("ldmatrix.sync.aligned.m8n8.x4.shared.b16 {%0,%1,%2,%3}, [%4];" \
                 : "=r"(r0), "=r"(r1), "=r"(r2), "=r"(r3) : "r"(addr))

#define LDSM2(r0, r1, addr) \
    asm volatile("ldmatrix.sync.aligned.m8n8.x2.shared.b16 {%0,%1}, [%2];" \
                 : "=r"(r0), "=r"(r1) : "r"(addr))

#define MMA16816(d, a, b0v, b1v) \
    asm volatile("mma.sync.aligned.m16n8k16.row.col.f32.f16.f16.f32 " \
                 "{%0,%1,%2,%3}, {%4,%5,%6,%7}, {%8,%9}, {%0,%1,%2,%3};" \
                 : "+f"((d)[0]), "+f"((d)[1]), "+f"((d)[2]), "+f"((d)[3]) \
                 : "r"((a)[0]), "r"((a)[1]), "r"((a)[2]), "r"((a)[3]), \
                   "r"(b0v), "r"(b1v))

#define SWZ(o) ((o) ^ (((o) >> 3) & 0x70))

__device__ __forceinline__ float sigm(float x) { return 1.0f / (1.0f + expf(-x)); }

// ---------------------------------------------------------------------------
// Pack A = fp16([input | h2_fl])
// ---------------------------------------------------------------------------
__global__ void prep_kernel(const float* __restrict__ inp,
                            const int*   __restrict__ hidden)
{
    int idx = blockIdx.x * 256 + threadIdx.x;      // 0 .. B_*KD-1
    int i = idx >> 11;
    int k = idx & 2047;
    float x = (k < 1024) ? inp[(size_t)i * 1024 + k]
                         : (float)hidden[(size_t)i * 4096 + k] * (1.0f / 8388608.0f);
    g_A[idx] = __float2half_rn(x);
}

// ---------------------------------------------------------------------------
// W1,W2 -> fp16 (one launch)
// ---------------------------------------------------------------------------
__global__ void wconv_kernel(const float* __restrict__ W1src,
                             const float* __restrict__ W2src)
{
    int idx = blockIdx.x * 256 + threadIdx.x;      // 0 .. 2*ND*KD-1
    constexpr int HALF = ND * KD;
    if (idx < HALF) g_W1[idx] = __float2half_rn(W1src[idx]);
    else            g_W2[idx - HALF] = __float2half_rn(W2src[idx - HALF]);
}

// ---------------------------------------------------------------------------
// Fused GEMM + fixed-point half-step.
// CTA: M=128 batch rows x 32 j-columns x ALL 5 gates (B tile = 160 W rows).
// 8 warps: wm = (wid&1)*64, j-slice wjj = (wid>>1)*8.
// K-chunk 64, SW128 swizzle, 3-stage cp.async, one barrier per chunk.
// A source: chunks 0-15 from g_A (input); chunks 16-31 from g_A (step 0, h2)
// or g_Ah1 (step 1, h1) — disjoint buffer kills the cross-CTA WAR race.
// Epilogue performs the entire elementwise update in registers; step 0
// writes h1_fl ONLY to g_Ah1.
// ---------------------------------------------------------------------------
constexpr int TMM = 128;
constexpr int A_BYTES = TMM * 128;                 // 16384 per stage
constexpr int B_BYTES = 160 * 128;                 // 20480 per stage
constexpr int STAGE_BYTES = A_BYTES + B_BYTES;     // 36864
constexpr int SMEM_TOTAL = 3 * STAGE_BYTES;        // 110592
constexpr int NCHUNK = KD / 64;                    // 32

__global__ __launch_bounds__(256, 2)
void gemm_fused_kernel(int step, const float* __restrict__ bias,
                       const int* __restrict__ hidden,
                       float* __restrict__ out)
{
    extern __shared__ char smem[];
    __shared__ double sred[256];
    const uint32_t sb = smem_u32(smem);
    const int tid  = threadIdx.x;
    const int wid  = tid >> 5;
    const int lane = tid & 31;
    const int bm  = blockIdx.y * TMM;
    const int bj0 = blockIdx.x * 32;
    const __half* __restrict__ Wg = step ? g_W2 : g_W1;

    // ---- producer setup: 4 A + 5 B cp.async per thread per stage ----
    const int prow = tid >> 3;                     // 0..31
    const int pgrp = tid & 7;                      // 0..7
    const char* Abase  = (const char*)(g_A   + (size_t)(bm + prow) * KD) + pgrp * 16;
    const char* Hbase  = (const char*)(g_Ah1 + (size_t)(bm + prow) * G_) + pgrp * 16;
    const char* Bbase  = (const char*)(Wg + (size_t)(bj0 + prow) * KD) + pgrp * 16;
    const uint32_t dA = SWZ((uint32_t)(prow * 128 + pgrp * 16));   // row step 32 is SWZ-safe
    constexpr size_t ASTRIDE = (size_t)32 * KD * 2;                // +32 rows in g_A
    constexpr size_t HSTRIDE = (size_t)32 * G_ * 2;                // +32 rows in g_Ah1
    constexpr size_t BSTRIDE = (size_t)1024 * KD * 2;              // next gate
    const bool useH = (step != 0);

    // ---- consumer setup ----
    const int wm  = (wid & 1) * 64;                // warp M offset
    const int wjj = (wid >> 1) * 8;                // warp j-slice
    const int q   = lane >> 3;                     // quad
    const int l7  = lane & 7;

    uint32_t a_rt[4], a_xor[4];
#pragma unroll
    for (int mt = 0; mt < 4; mt++) {
        const int row = wm + mt * 16 + l7 + (q & 1) * 8;
        a_rt[mt]  = (uint32_t)row * 128;
        a_xor[mt] = (uint32_t)(row & 7) * 16;
    }
    const uint32_t a_kh = (uint32_t)(q >> 1) * 16;

    // B: 5 gate blocks of 8 rows each; ldmatrix.x2 (lanes 0-15 give addresses)
    uint32_t b_rt[5];
#pragma unroll
    for (int gt = 0; gt < 5; gt++)
        b_rt[gt] = (uint32_t)(A_BYTES + (gt * 32 + wjj + l7) * 128);
    const uint32_t b_xor = (uint32_t)l7 * 16;
    const uint32_t b_kh  = (uint32_t)(q & 1) * 16;

    float acc[4][5][4];
#pragma unroll
    for (int mt = 0; mt < 4; mt++)
#pragma unroll
        for (int gt = 0; gt < 5; gt++)
#pragma unroll
            for (int r = 0; r < 4; r++) acc[mt][gt][r] = 0.0f;

    // ---- prologue: chunks 0,1 into stages 0,1 (always low chunks -> g_A) ----
#pragma unroll
    for (int s = 0; s < 2; s++) {
        const uint32_t sdst = sb + s * STAGE_BYTES;
        const size_t koff = (size_t)s * 128;
#pragma unroll
        for (int i = 0; i < 4; i++)
            cp_async16(sdst + dA + i * 4096, Abase + i * ASTRIDE + koff);
#pragma unroll
        for (int j = 0; j < 5; j++)
            cp_async16(sdst + A_BYTES + dA + j * 4096, Bbase + j * BSTRIDE + koff);
        CP_COMMIT();
    }

    // ---- main loop: one barrier per chunk ----
    int sc = 0, sl = 2;
    for (int c = 0; c < NCHUNK; c++) {
        CP_WAIT(1);
        __syncthreads();
        if (c + 2 < NCHUNK) {
            const uint32_t sdst = sb + sl * STAGE_BYTES;
            const int cl = c + 2;
            if (useH && cl >= 16) {                 // h half from g_Ah1
                const size_t koff = (size_t)(cl - 16) * 128;
#pragma unroll
                for (int i = 0; i < 4; i++)
                    cp_async16(sdst + dA + i * 4096, Hbase + i * HSTRIDE + koff);
            } else {                                // input half / step-0 h2 from g_A
                const size_t koff = (size_t)cl * 128;
#pragma unroll
                for (int i = 0; i < 4; i++)
                    cp_async16(sdst + dA + i * 4096, Abase + i * ASTRIDE + koff);
            }
            const size_t koffB = (size_t)cl * 128;
#pragma unroll
            for (int j = 0; j < 5; j++)
                cp_async16(sdst + A_BYTES + dA + j * 4096, Bbase + j * BSTRIDE + koffB);
        }
        CP_COMMIT();

        const uint32_t sA = sb + sc * STAGE_BYTES;
#pragma unroll
        for (int kk = 0; kk < 4; kk++) {
            const uint32_t kb = kk * 32;
            uint32_t af[4][4];
#pragma unroll
            for (int mt = 0; mt < 4; mt++)
                LDSM4(af[mt][0], af[mt][1], af[mt][2], af[mt][3],
                      sA + a_rt[mt] + ((kb + a_kh) ^ a_xor[mt]));
            uint32_t bf[5][2];
#pragma unroll
            for (int gt = 0; gt < 5; gt++)
                LDSM2(bf[gt][0], bf[gt][1],
                      sA + b_rt[gt] + ((kb + b_kh) ^ b_xor));
#pragma unroll
            for (int mt = 0; mt < 4; mt++)
#pragma unroll
                for (int gt = 0; gt < 5; gt++)
                    MMA16816(acc[mt][gt], af[mt], bf[gt][0], bf[gt][1]);
        }

        sc = (sc == 2) ? 0 : sc + 1;
        sl = (sl == 2) ? 0 : sl + 1;
    }

    // ---- fused elementwise epilogue (all 5 gates resident in registers) ----
    const int trow = lane >> 2;
    const int tcol = (lane & 3) * 2;
    const int jb   = bj0 + wjj + tcol;             // global j for cc=0

    float bz[5][2];
#pragma unroll
    for (int gt = 0; gt < 5; gt++) {
        bz[gt][0] = __ldg(bias + gt * 1024 + jb);
        bz[gt][1] = __ldg(bias + gt * 1024 + jb + 1);
    }

    double lsum = 0.0;
#pragma unroll
    for (int mt = 0; mt < 4; mt++) {
#pragma unroll
        for (int r2 = 0; r2 < 2; r2++) {
            const int i = bm + wm + mt * 16 + trow + r2 * 8;
            const int* hrow = hidden + (size_t)i * 4096;
            const size_t ro = (size_t)i * 4096;
            const size_t oo = OUT_OH + (size_t)i * 2048 + (size_t)step * 1024;
#pragma unroll
            for (int cc = 0; cc < 2; cc++) {
                const int j = jb + cc;
                const int a = r2 * 2 + cc;
                const float xz = acc[mt][0][a] + bz[0][cc];
                const float xg = acc[mt][1][a] + bz[1][cc];
                const float xf = acc[mt][2][a] + bz[2][cc];
                const float xo = acc[mt][3][a] + bz[3][cc];
                const float xp = acc[mt][4][a] + bz[4][cc];

                const float z  = 0.96875f * sigm(xz) + 0.03125f;
                const float gg = tanhf(xg);
                const float f  = sigm(xf);
                const float o  = sigm(xo);
                const float p  = 0.96875f * sigm(xp) + 0.03125f;

                int zi = (int)(z * 1024.0f); if (zi < 1) zi = 1;
                int pi = (int)(p * 1024.0f); if (pi < 1) pi = 1;

                const int cv = hrow[(2 + step) * 1024 + j];
                const int hv = hrow[step * 1024 + j];

                const int cn = (int)(((long long)cv * (long long)zi) >> 10)
                             + (int)(f * gg * 8388608.0f);
                const float cfl = (float)cn * (1.0f / 8388608.0f);
                const int hn = (int)(((long long)hv * (long long)pi) >> 10)
                             + (int)(o * tanhf(cfl) * 8388608.0f);

                out[ro + (size_t)step * 1024 + j]       = (float)hn;
                out[ro + (size_t)(2 + step) * 1024 + j] = (float)cn;
                const float hfl = (float)hn * (1.0f / 8388608.0f);
                out[oo + j] = hfl;
                if (step == 0)
                    g_Ah1[(size_t)i * G_ + j] = __float2half_rn(hfl);

                lsum += (double)(logf(z) + logf(p));
            }
        }
    }

    // ---- deterministic per-CTA log reduction ----
    sred[tid] = lsum;
    __syncthreads();
#pragma unroll
    for (int s = 128; s > 0; s >>= 1) {
        if (tid < s) sred[tid] += sred[tid + s];
        __syncthreads();
    }
    if (tid == 0)
        g_part[step * 1024 + blockIdx.y * gridDim.x + blockIdx.x] = sred[0];
}

// ---------------------------------------------------------------------------
// Final scalar: optimal_bits = -(sum of logs) / ln2
// ---------------------------------------------------------------------------
__global__ void bits_kernel(float* __restrict__ out, long long last_idx)
{
    __shared__ double sred[256];
    const int tid = threadIdx.x;
    double s = 0.0;
    for (int i = tid; i < 2 * 1024; i += 256) s += g_part[i];
    sred[tid] = s;
    __syncthreads();
#pragma unroll
    for (int k = 128; k > 0; k >>= 1) {
        if (tid < k) sred[tid] += sred[tid + k];
        __syncthreads();
    }
    if (tid == 0)
        out[last_idx] = (float)(-sred[0] / 0.6931471805599453);
}

// ---------------------------------------------------------------------------
extern "C" void kernel_launch(void* const* d_in, const int* in_sizes, int n_in,
                              void* d_out, int out_size)
{
    const float* inp    = (const float*)d_in[0];   // (4096, 1024)
    const int*   hidden = (const int*)  d_in[1];   // (4096, 4096)
    const float* W1     = (const float*)d_in[2];   // (5120, 2048)
    const float* b1     = (const float*)d_in[3];
    const float* W2     = (const float*)d_in[4];
    const float* b2     = (const float*)d_in[5];
    float* out = (float*)d_out;

    static bool attr_set = false;
    if (!attr_set) {
        cudaFuncSetAttribute(gemm_fused_kernel,
                             cudaFuncAttributeMaxDynamicSharedMemorySize, SMEM_TOTAL);
        attr_set = true;
    }

    dim3 gemm_grid(G_ / 32, B_ / TMM);             // (32, 32)

    prep_kernel <<<(B_ * KD) / 256, 256>>>(inp, hidden);
    wconv_kernel<<<(2 * ND * KD) / 256, 256>>>(W1, W2);

    gemm_fused_kernel<<<gemm_grid, 256, SMEM_TOTAL>>>(0, b1, hidden, out);
    gemm_fused_kernel<<<gemm_grid, 256, SMEM_TOTAL>>>(1, b2, hidden, out);
    bits_kernel<<<1, 256>>>(out, (long long)out_size - 1);
}

// round 10
// speedup vs baseline: 1.3441x; 1.0988x over previous
#include <cuda_runtime.h>
#include <cuda_fp16.h>
#include <math.h>
#include <stdint.h>

// ---------------------------------------------------------------------------
// Problem constants
// ---------------------------------------------------------------------------
constexpr int B_  = 4096;    // batch
constexpr int G_  = 1024;    // gate width
constexpr int KD  = 2048;    // IN + g  (GEMM K)
constexpr int ND  = 5120;    // out_dim
constexpr long long OUT_OH = (long long)B_ * 4 * G_;

// ---------------------------------------------------------------------------
// Static scratch (no allocations allowed)
// ---------------------------------------------------------------------------
__device__ __align__(256) __half g_A  [(size_t)B_ * KD];   // [input | h2_fl] 16.8 MB
__device__ __align__(256) __half g_Ah1[(size_t)B_ * G_];   // h1_fl (step-1 h half) 8.4 MB
__device__ __align__(256) __half g_W1[(size_t)ND * KD];    // 21 MB
__device__ __align__(256) __half g_W2[(size_t)ND * KD];    // 21 MB
__device__ double g_part[2 * 1024];

// ---------------------------------------------------------------------------
// PTX helpers (all baseline sm_80+ features)
// ---------------------------------------------------------------------------
__device__ __forceinline__ uint32_t smem_u32(const void* p) {
    uint32_t a;
    asm("{ .reg .u64 t; cvta.to.shared.u64 t, %1; cvt.u32.u64 %0, t; }" : "=r"(a) : "l"(p));
    return a;
}
__device__ __forceinline__ void cp_async16(uint32_t dst, const void* src) {
    asm volatile("cp.async.cg.shared.global [%0], [%1], 16;" :: "r"(dst), "l"(src) : "memory");
}
#define CP_COMMIT()  asm volatile("cp.async.commit_group;" ::: "memory")
#define CP_WAIT(n)   asm volatile("cp.async.wait_group %0;" :: "n"(n) : "memory")

#define LDSM4(r0, r1, r2, r3, addr) \
    asm volatile("ldmatrix.sync.aligned.m8n8.x4.shared.b16 {%0,%1,%2,%3}, [%4];" \
                 : "=r"(r0), "=r"(r1), "=r"(r2), "=r"(r3) : "r"(addr))

#define MMA16816(d, a, b0v, b1v) \
    asm volatile("mma.sync.aligned.m16n8k16.row.col.f32.f16.f16.f32 " \
                 "{%0,%1,%2,%3}, {%4,%5,%6,%7}, {%8,%9}, {%0,%1,%2,%3};" \
                 : "+f"((d)[0]), "+f"((d)[1]), "+f"((d)[2]), "+f"((d)[3]) \
                 : "r"((a)[0]), "r"((a)[1]), "r"((a)[2]), "r"((a)[3]), \
                   "r"(b0v), "r"(b1v))

#define SWZ(o) ((o) ^ (((o) >> 3) & 0x70))

__device__ __forceinline__ float sigm(float x) { return 1.0f / (1.0f + expf(-x)); }

// ---------------------------------------------------------------------------
// Pack A = fp16([input | h2_fl]) — 8 elements per thread, 16B stores
// ---------------------------------------------------------------------------
__global__ void prep_kernel(const float* __restrict__ inp,
                            const int*   __restrict__ hidden)
{
    const int g = blockIdx.x * 256 + threadIdx.x;  // 0 .. B_*KD/8-1
    const int idx = g * 8;
    const int i = idx >> 11;
    const int k = idx & 2047;                      // multiple of 8; no boundary straddle
    __half h[8];
    if (k < 1024) {
        const float4 f0 = *(const float4*)(inp + (size_t)i * 1024 + k);
        const float4 f1 = *(const float4*)(inp + (size_t)i * 1024 + k + 4);
        h[0]=__float2half_rn(f0.x); h[1]=__float2half_rn(f0.y);
        h[2]=__float2half_rn(f0.z); h[3]=__float2half_rn(f0.w);
        h[4]=__float2half_rn(f1.x); h[5]=__float2half_rn(f1.y);
        h[6]=__float2half_rn(f1.z); h[7]=__float2half_rn(f1.w);
    } else {
        const int4 v0 = *(const int4*)(hidden + (size_t)i * 4096 + k);
        const int4 v1 = *(const int4*)(hidden + (size_t)i * 4096 + k + 4);
        const float s = 1.0f / 8388608.0f;
        h[0]=__float2half_rn((float)v0.x*s); h[1]=__float2half_rn((float)v0.y*s);
        h[2]=__float2half_rn((float)v0.z*s); h[3]=__float2half_rn((float)v0.w*s);
        h[4]=__float2half_rn((float)v1.x*s); h[5]=__float2half_rn((float)v1.y*s);
        h[6]=__float2half_rn((float)v1.z*s); h[7]=__float2half_rn((float)v1.w*s);
    }
    *(uint4*)(g_A + idx) = *(const uint4*)h;
}

// ---------------------------------------------------------------------------
// W1,W2 -> fp16, 8 elements per thread
// ---------------------------------------------------------------------------
__global__ void wconv_kernel(const float* __restrict__ W1src,
                             const float* __restrict__ W2src)
{
    constexpr size_t HALF = (size_t)ND * KD;
    const size_t idx = ((size_t)blockIdx.x * 256 + threadIdx.x) * 8;
    const float* src = (idx < HALF) ? (W1src + idx) : (W2src + (idx - HALF));
    __half* dst = (idx < HALF) ? (g_W1 + idx) : (g_W2 + (idx - HALF));
    const float4 f0 = *(const float4*)(src);
    const float4 f1 = *(const float4*)(src + 4);
    __half h[8];
    h[0]=__float2half_rn(f0.x); h[1]=__float2half_rn(f0.y);
    h[2]=__float2half_rn(f0.z); h[3]=__float2half_rn(f0.w);
    h[4]=__float2half_rn(f1.x); h[5]=__float2half_rn(f1.y);
    h[6]=__float2half_rn(f1.z); h[7]=__float2half_rn(f1.w);
    *(uint4*)dst = *(const uint4*)h;
}

// ---------------------------------------------------------------------------
// Fused GEMM + fixed-point half-step.
// CTA: M=128 batch rows x 32 j-columns x ALL 5 gates (B tile = 160 W rows).
// 8 warps: wm = (wid&1)*64, j-slice wjj = (wid>>1)*8.
// B fragments: 2 gates packed per ldmatrix.x4 (lanes 0-15 gate 2i, 16-31 gate 2i+1).
// K-chunk 64, SW128 swizzle, 3-stage cp.async, one barrier per chunk.
// Step-1 h-half read from disjoint g_Ah1 (no cross-CTA WAR).
// ---------------------------------------------------------------------------
constexpr int TMM = 128;
constexpr int A_BYTES = TMM * 128;                 // 16384 per stage
constexpr int B_BYTES = 160 * 128;                 // 20480 per stage
constexpr int STAGE_BYTES = A_BYTES + B_BYTES;     // 36864
constexpr int SMEM_TOTAL = 3 * STAGE_BYTES;        // 110592
constexpr int NCHUNK = KD / 64;                    // 32

__global__ __launch_bounds__(256, 2)
void gemm_fused_kernel(int step, const float* __restrict__ bias,
                       const int* __restrict__ hidden,
                       float* __restrict__ out)
{
    extern __shared__ char smem[];
    __shared__ double sred[256];
    const uint32_t sb = smem_u32(smem);
    const int tid  = threadIdx.x;
    const int wid  = tid >> 5;
    const int lane = tid & 31;
    const int bm  = blockIdx.y * TMM;
    const int bj0 = blockIdx.x * 32;
    const __half* __restrict__ Wg = step ? g_W2 : g_W1;

    // ---- producer setup: 4 A + 5 B cp.async per thread per stage ----
    const int prow = tid >> 3;                     // 0..31
    const int pgrp = tid & 7;                      // 0..7
    const char* Abase  = (const char*)(g_A   + (size_t)(bm + prow) * KD) + pgrp * 16;
    const char* Hbase  = (const char*)(g_Ah1 + (size_t)(bm + prow) * G_) + pgrp * 16;
    const char* Bbase  = (const char*)(Wg + (size_t)(bj0 + prow) * KD) + pgrp * 16;
    const uint32_t dA = SWZ((uint32_t)(prow * 128 + pgrp * 16));   // row step 32 is SWZ-safe
    constexpr size_t ASTRIDE = (size_t)32 * KD * 2;                // +32 rows in g_A
    constexpr size_t HSTRIDE = (size_t)32 * G_ * 2;                // +32 rows in g_Ah1
    constexpr size_t BSTRIDE = (size_t)1024 * KD * 2;              // next gate
    const bool useH = (step != 0);

    // ---- consumer setup ----
    const int wm  = (wid & 1) * 64;                // warp M offset
    const int wjj = (wid >> 1) * 8;                // warp j-slice
    const int q   = lane >> 3;                     // quad
    const int l7  = lane & 7;

    uint32_t a_rt[4], a_xor[4];
#pragma unroll
    for (int mt = 0; mt < 4; mt++) {
        const int row = wm + mt * 16 + l7 + (q & 1) * 8;
        a_rt[mt]  = (uint32_t)row * 128;
        a_xor[mt] = (uint32_t)(row & 7) * 16;
    }
    const uint32_t a_kh = (uint32_t)(q >> 1) * 16;

    // B: packed 2-gate ldmatrix.x4. Lane group (lane>>4) selects gate within pair;
    // ((lane>>3)&1) selects k-low/k-high half (+16B). Row within gate block = wjj + l7.
    uint32_t b_rt[3];
#pragma unroll
    for (int i = 0; i < 3; i++) {
        const int gate = (i < 2) ? (2 * i + ((lane >> 4) & 1)) : 4;
        b_rt[i] = (uint32_t)(A_BYTES + (gate * 32 + wjj + l7) * 128);
    }
    const uint32_t b_xor = (uint32_t)l7 * 16;
    const uint32_t b_kh  = (uint32_t)((lane >> 3) & 1) * 16;

    float acc[4][5][4];
#pragma unroll
    for (int mt = 0; mt < 4; mt++)
#pragma unroll
        for (int gt = 0; gt < 5; gt++)
#pragma unroll
            for (int r = 0; r < 4; r++) acc[mt][gt][r] = 0.0f;

    // ---- prologue: chunks 0,1 into stages 0,1 (low chunks -> g_A) ----
#pragma unroll
    for (int s = 0; s < 2; s++) {
        const uint32_t sdst = sb + s * STAGE_BYTES;
        const size_t koff = (size_t)s * 128;
#pragma unroll
        for (int i = 0; i < 4; i++)
            cp_async16(sdst + dA + i * 4096, Abase + i * ASTRIDE + koff);
#pragma unroll
        for (int j = 0; j < 5; j++)
            cp_async16(sdst + A_BYTES + dA + j * 4096, Bbase + j * BSTRIDE + koff);
        CP_COMMIT();
    }

    // ---- main loop: one barrier per chunk ----
    int sc = 0, sl = 2;
    for (int c = 0; c < NCHUNK; c++) {
        CP_WAIT(1);
        __syncthreads();
        if (c + 2 < NCHUNK) {
            const uint32_t sdst = sb + sl * STAGE_BYTES;
            const int cl = c + 2;
            if (useH && cl >= 16) {                 // h half from g_Ah1
                const size_t koff = (size_t)(cl - 16) * 128;
#pragma unroll
                for (int i = 0; i < 4; i++)
                    cp_async16(sdst + dA + i * 4096, Hbase + i * HSTRIDE + koff);
            } else {                                // input half / step-0 h2 from g_A
                const size_t koff = (size_t)cl * 128;
#pragma unroll
                for (int i = 0; i < 4; i++)
                    cp_async16(sdst + dA + i * 4096, Abase + i * ASTRIDE + koff);
            }
            const size_t koffB = (size_t)cl * 128;
#pragma unroll
            for (int j = 0; j < 5; j++)
                cp_async16(sdst + A_BYTES + dA + j * 4096, Bbase + j * BSTRIDE + koffB);
        }
        CP_COMMIT();

        const uint32_t sA = sb + sc * STAGE_BYTES;
#pragma unroll
        for (int kk = 0; kk < 4; kk++) {
            const uint32_t kb = kk * 32;
            uint32_t af[4][4];
#pragma unroll
            for (int mt = 0; mt < 4; mt++)
                LDSM4(af[mt][0], af[mt][1], af[mt][2], af[mt][3],
                      sA + a_rt[mt] + ((kb + a_kh) ^ a_xor[mt]));
            uint32_t bf[3][4];                      // [pair][r]; pair i = gates 2i,2i+1
#pragma unroll
            for (int i = 0; i < 3; i++)
                LDSM4(bf[i][0], bf[i][1], bf[i][2], bf[i][3],
                      sA + b_rt[i] + ((kb + b_kh) ^ b_xor));
#pragma unroll
            for (int mt = 0; mt < 4; mt++)
#pragma unroll
                for (int gt = 0; gt < 5; gt++)
                    MMA16816(acc[mt][gt], af[mt],
                             bf[gt >> 1][(gt & 1) * 2],
                             bf[gt >> 1][(gt & 1) * 2 + 1]);
        }

        sc = (sc == 2) ? 0 : sc + 1;
        sl = (sl == 2) ? 0 : sl + 1;
    }

    // ---- fused elementwise epilogue (all 5 gates resident in registers) ----
    const int trow = lane >> 2;
    const int tcol = (lane & 3) * 2;
    const int jb   = bj0 + wjj + tcol;             // global j for cc=0

    float bz[5][2];
#pragma unroll
    for (int gt = 0; gt < 5; gt++) {
        bz[gt][0] = __ldg(bias + gt * 1024 + jb);
        bz[gt][1] = __ldg(bias + gt * 1024 + jb + 1);
    }

    double lsum = 0.0;
#pragma unroll
    for (int mt = 0; mt < 4; mt++) {
#pragma unroll
        for (int r2 = 0; r2 < 2; r2++) {
            const int i = bm + wm + mt * 16 + trow + r2 * 8;
            const int* hrow = hidden + (size_t)i * 4096;
            const size_t ro = (size_t)i * 4096;
            const size_t oo = OUT_OH + (size_t)i * 2048 + (size_t)step * 1024;
#pragma unroll
            for (int cc = 0; cc < 2; cc++) {
                const int j = jb + cc;
                const int a = r2 * 2 + cc;
                const float xz = acc[mt][0][a] + bz[0][cc];
                const float xg = acc[mt][1][a] + bz[1][cc];
                const float xf = acc[mt][2][a] + bz[2][cc];
                const float xo = acc[mt][3][a] + bz[3][cc];
                const float xp = acc[mt][4][a] + bz[4][cc];

                const float z  = 0.96875f * sigm(xz) + 0.03125f;
                const float gg = tanhf(xg);
                const float f  = sigm(xf);
                const float o  = sigm(xo);
                const float p  = 0.96875f * sigm(xp) + 0.03125f;

                int zi = (int)(z * 1024.0f); if (zi < 1) zi = 1;
                int pi = (int)(p * 1024.0f); if (pi < 1) pi = 1;

                const int cv = hrow[(2 + step) * 1024 + j];
                const int hv = hrow[step * 1024 + j];

                const int cn = (int)(((long long)cv * (long long)zi) >> 10)
                             + (int)(f * gg * 8388608.0f);
                const float cfl = (float)cn * (1.0f / 8388608.0f);
                const int hn = (int)(((long long)hv * (long long)pi) >> 10)
                             + (int)(o * tanhf(cfl) * 8388608.0f);

                out[ro + (size_t)step * 1024 + j]       = (float)hn;
                out[ro + (size_t)(2 + step) * 1024 + j] = (float)cn;
                const float hfl = (float)hn * (1.0f / 8388608.0f);
                out[oo + j] = hfl;
                if (step == 0)
                    g_Ah1[(size_t)i * G_ + j] = __float2half_rn(hfl);

                lsum += (double)(logf(z) + logf(p));
            }
        }
    }

    // ---- deterministic per-CTA log reduction ----
    sred[tid] = lsum;
    __syncthreads();
#pragma unroll
    for (int s = 128; s > 0; s >>= 1) {
        if (tid < s) sred[tid] += sred[tid + s];
        __syncthreads();
    }
    if (tid == 0)
        g_part[step * 1024 + blockIdx.y * gridDim.x + blockIdx.x] = sred[0];
}

// ---------------------------------------------------------------------------
// Final scalar: optimal_bits = -(sum of logs) / ln2
// ---------------------------------------------------------------------------
__global__ void bits_kernel(float* __restrict__ out, long long last_idx)
{
    __shared__ double sred[256];
    const int tid = threadIdx.x;
    double s = 0.0;
    for (int i = tid; i < 2 * 1024; i += 256) s += g_part[i];
    sred[tid] = s;
    __syncthreads();
#pragma unroll
    for (int k = 128; k > 0; k >>= 1) {
        if (tid < k) sred[tid] += sred[tid + k];
        __syncthreads();
    }
    if (tid == 0)
        out[last_idx] = (float)(-sred[0] / 0.6931471805599453);
}

// ---------------------------------------------------------------------------
extern "C" void kernel_launch(void* const* d_in, const int* in_sizes, int n_in,
                              void* d_out, int out_size)
{
    const float* inp    = (const float*)d_in[0];   // (4096, 1024)
    const int*   hidden = (const int*)  d_in[1];   // (4096, 4096)
    const float* W1     = (const float*)d_in[2];   // (5120, 2048)
    const float* b1     = (const float*)d_in[3];
    const float* W2     = (const float*)d_in[4];
    const float* b2     = (const float*)d_in[5];
    float* out = (float*)d_out;

    static bool attr_set = false;
    if (!attr_set) {
        cudaFuncSetAttribute(gemm_fused_kernel,
                             cudaFuncAttributeMaxDynamicSharedMemorySize, SMEM_TOTAL);
        attr_set = true;
    }

    dim3 gemm_grid(G_ / 32, B_ / TMM);             // (32, 32)

    prep_kernel <<<(B_ * KD) / (256 * 8), 256>>>(inp, hidden);
    wconv_kernel<<<(2 * ND * KD) / (256 * 8), 256>>>(W1, W2);

    gemm_fused_kernel<<<gemm_grid, 256, SMEM_TOTAL>>>(0, b1, hidden, out);
    gemm_fused_kernel<<<gemm_grid, 256, SMEM_TOTAL>>>(1, b2, hidden, out);
    bits_kernel<<<1, 256>>>(out, (long long)out_size - 1);
}

// round 11
// speedup vs baseline: 1.3485x; 1.0033x over previous
#include <cuda_runtime.h>
#include <cuda_fp16.h>
#include <math.h>
#include <stdint.h>

// ---------------------------------------------------------------------------
// Problem constants
// ---------------------------------------------------------------------------
constexpr int B_  = 4096;    // batch
constexpr int G_  = 1024;    // gate width
constexpr int KD  = 2048;    // IN + g  (GEMM K)
constexpr int ND  = 5120;    // out_dim
constexpr long long OUT_OH = (long long)B_ * 4 * G_;

// ---------------------------------------------------------------------------
// Static scratch (no allocations allowed)
// ---------------------------------------------------------------------------
__device__ __align__(256) __half g_A  [(size_t)B_ * KD];   // [input | h2_fl] 16.8 MB
__device__ __align__(256) __half g_Ah1[(size_t)B_ * G_];   // h1_fl (step-1 h half) 8.4 MB
__device__ __align__(256) __half g_W1[(size_t)ND * KD];    // 21 MB
__device__ __align__(256) __half g_W2[(size_t)ND * KD];    // 21 MB
__device__ double g_part[2 * 1024];

// ---------------------------------------------------------------------------
// PTX helpers (all baseline sm_80+ features)
// ---------------------------------------------------------------------------
__device__ __forceinline__ uint32_t smem_u32(const void* p) {
    uint32_t a;
    asm("{ .reg .u64 t; cvta.to.shared.u64 t, %1; cvt.u32.u64 %0, t; }" : "=r"(a) : "l"(p));
    return a;
}
__device__ __forceinline__ void cp_async16(uint32_t dst, const void* src) {
    asm volatile("cp.async.cg.shared.global [%0], [%1], 16;" :: "r"(dst), "l"(src) : "memory");
}
#define CP_COMMIT()  asm volatile("cp.async.commit_group;" ::: "memory")
#define CP_WAIT(n)   asm volatile("cp.async.wait_group %0;" :: "n"(n) : "memory")

#define LDSM4(r0, r1, r2, r3, addr) \
    asm volatile("ldmatrix.sync.aligned.m8n8.x4.shared.b16 {%0,%1,%2,%3}, [%4];" \
                 : "=r"(r0), "=r"(r1), "=r"(r2), "=r"(r3) : "r"(addr))

#define LDSM2(r0, r1, addr) \
    asm volatile("ldmatrix.sync.aligned.m8n8.x2.shared.b16 {%0,%1}, [%2];" \
                 : "=r"(r0), "=r"(r1) : "r"(addr))

#define MMA16816(d, a, b0v, b1v) \
    asm volatile("mma.sync.aligned.m16n8k16.row.col.f32.f16.f16.f32 " \
                 "{%0,%1,%2,%3}, {%4,%5,%6,%7}, {%8,%9}, {%0,%1,%2,%3};" \
                 : "+f"((d)[0]), "+f"((d)[1]), "+f"((d)[2]), "+f"((d)[3]) \
                 : "r"((a)[0]), "r"((a)[1]), "r"((a)[2]), "r"((a)[3]), \
                   "r"(b0v), "r"(b1v))

#define SWZ(o) ((o) ^ (((o) >> 3) & 0x70))

__device__ __forceinline__ float sigm(float x) { return 1.0f / (1.0f + expf(-x)); }

// ---------------------------------------------------------------------------
// Pack A = fp16([input | h2_fl]) — 8 elements per thread, 16B stores
// ---------------------------------------------------------------------------
__global__ void prep_kernel(const float* __restrict__ inp,
                            const int*   __restrict__ hidden)
{
    const int g = blockIdx.x * 256 + threadIdx.x;  // 0 .. B_*KD/8-1
    const int idx = g * 8;
    const int i = idx >> 11;
    const int k = idx & 2047;                      // multiple of 8; no boundary straddle
    __half h[8];
    if (k < 1024) {
        const float4 f0 = *(const float4*)(inp + (size_t)i * 1024 + k);
        const float4 f1 = *(const float4*)(inp + (size_t)i * 1024 + k + 4);
        h[0]=__float2half_rn(f0.x); h[1]=__float2half_rn(f0.y);
        h[2]=__float2half_rn(f0.z); h[3]=__float2half_rn(f0.w);
        h[4]=__float2half_rn(f1.x); h[5]=__float2half_rn(f1.y);
        h[6]=__float2half_rn(f1.z); h[7]=__float2half_rn(f1.w);
    } else {
        const int4 v0 = *(const int4*)(hidden + (size_t)i * 4096 + k);
        const int4 v1 = *(const int4*)(hidden + (size_t)i * 4096 + k + 4);
        const float s = 1.0f / 8388608.0f;
        h[0]=__float2half_rn((float)v0.x*s); h[1]=__float2half_rn((float)v0.y*s);
        h[2]=__float2half_rn((float)v0.z*s); h[3]=__float2half_rn((float)v0.w*s);
        h[4]=__float2half_rn((float)v1.x*s); h[5]=__float2half_rn((float)v1.y*s);
        h[6]=__float2half_rn((float)v1.z*s); h[7]=__float2half_rn((float)v1.w*s);
    }
    *(uint4*)(g_A + idx) = *(const uint4*)h;
}

// ---------------------------------------------------------------------------
// W1,W2 -> fp16, 8 elements per thread
// ---------------------------------------------------------------------------
__global__ void wconv_kernel(const float* __restrict__ W1src,
                             const float* __restrict__ W2src)
{
    constexpr size_t HALF = (size_t)ND * KD;
    const size_t idx = ((size_t)blockIdx.x * 256 + threadIdx.x) * 8;
    const float* src = (idx < HALF) ? (W1src + idx) : (W2src + (idx - HALF));
    __half* dst = (idx < HALF) ? (g_W1 + idx) : (g_W2 + (idx - HALF));
    const float4 f0 = *(const float4*)(src);
    const float4 f1 = *(const float4*)(src + 4);
    __half h[8];
    h[0]=__float2half_rn(f0.x); h[1]=__float2half_rn(f0.y);
    h[2]=__float2half_rn(f0.z); h[3]=__float2half_rn(f0.w);
    h[4]=__float2half_rn(f1.x); h[5]=__float2half_rn(f1.y);
    h[6]=__float2half_rn(f1.z); h[7]=__float2half_rn(f1.w);
    *(uint4*)dst = *(const uint4*)h;
}

// ---------------------------------------------------------------------------
// Fused GEMM + fixed-point half-step (R9 GEMM core — the measured-fastest).
// CTA: M=128 batch rows x 32 j-columns x ALL 5 gates (B tile = 160 W rows).
// 8 warps: wm = (wid&1)*64, j-slice wjj = (wid>>1)*8.
// B: 5 gate blocks, one LDSM2 each per k16 slice.
// K-chunk 64, SW128 swizzle, 3-stage cp.async, one barrier per chunk.
// Step-1 h-half read from disjoint g_Ah1 (no cross-CTA WAR).
// ---------------------------------------------------------------------------
constexpr int TMM = 128;
constexpr int A_BYTES = TMM * 128;                 // 16384 per stage
constexpr int B_BYTES = 160 * 128;                 // 20480 per stage
constexpr int STAGE_BYTES = A_BYTES + B_BYTES;     // 36864
constexpr int SMEM_TOTAL = 3 * STAGE_BYTES;        // 110592
constexpr int NCHUNK = KD / 64;                    // 32

__global__ __launch_bounds__(256, 2)
void gemm_fused_kernel(int step, const float* __restrict__ bias,
                       const int* __restrict__ hidden,
                       float* __restrict__ out)
{
    extern __shared__ char smem[];
    __shared__ double sred[256];
    const uint32_t sb = smem_u32(smem);
    const int tid  = threadIdx.x;
    const int wid  = tid >> 5;
    const int lane = tid & 31;
    const int bm  = blockIdx.y * TMM;
    const int bj0 = blockIdx.x * 32;
    const __half* __restrict__ Wg = step ? g_W2 : g_W1;

    // ---- producer setup: 4 A + 5 B cp.async per thread per stage ----
    const int prow = tid >> 3;                     // 0..31
    const int pgrp = tid & 7;                      // 0..7
    const char* Abase  = (const char*)(g_A   + (size_t)(bm + prow) * KD) + pgrp * 16;
    const char* Hbase  = (const char*)(g_Ah1 + (size_t)(bm + prow) * G_) + pgrp * 16;
    const char* Bbase  = (const char*)(Wg + (size_t)(bj0 + prow) * KD) + pgrp * 16;
    const uint32_t dA = SWZ((uint32_t)(prow * 128 + pgrp * 16));   // row step 32 is SWZ-safe
    constexpr size_t ASTRIDE = (size_t)32 * KD * 2;                // +32 rows in g_A
    constexpr size_t HSTRIDE = (size_t)32 * G_ * 2;                // +32 rows in g_Ah1
    constexpr size_t BSTRIDE = (size_t)1024 * KD * 2;              // next gate
    const bool useH = (step != 0);

    // ---- consumer setup ----
    const int wm  = (wid & 1) * 64;                // warp M offset
    const int wjj = (wid >> 1) * 8;                // warp j-slice
    const int q   = lane >> 3;                     // quad
    const int l7  = lane & 7;

    uint32_t a_rt[4], a_xor[4];
#pragma unroll
    for (int mt = 0; mt < 4; mt++) {
        const int row = wm + mt * 16 + l7 + (q & 1) * 8;
        a_rt[mt]  = (uint32_t)row * 128;
        a_xor[mt] = (uint32_t)(row & 7) * 16;
    }
    const uint32_t a_kh = (uint32_t)(q >> 1) * 16;

    // B: 5 gate blocks of 8 rows each; ldmatrix.x2 (lanes 0-15 give addresses)
    uint32_t b_rt[5];
#pragma unroll
    for (int gt = 0; gt < 5; gt++)
        b_rt[gt] = (uint32_t)(A_BYTES + (gt * 32 + wjj + l7) * 128);
    const uint32_t b_xor = (uint32_t)l7 * 16;
    const uint32_t b_kh  = (uint32_t)(q & 1) * 16;

    float acc[4][5][4];
#pragma unroll
    for (int mt = 0; mt < 4; mt++)
#pragma unroll
        for (int gt = 0; gt < 5; gt++)
#pragma unroll
            for (int r = 0; r < 4; r++) acc[mt][gt][r] = 0.0f;

    // ---- prologue: chunks 0,1 into stages 0,1 (low chunks -> g_A) ----
#pragma unroll
    for (int s = 0; s < 2; s++) {
        const uint32_t sdst = sb + s * STAGE_BYTES;
        const size_t koff = (size_t)s * 128;
#pragma unroll
        for (int i = 0; i < 4; i++)
            cp_async16(sdst + dA + i * 4096, Abase + i * ASTRIDE + koff);
#pragma unroll
        for (int j = 0; j < 5; j++)
            cp_async16(sdst + A_BYTES + dA + j * 4096, Bbase + j * BSTRIDE + koff);
        CP_COMMIT();
    }

    // ---- main loop: one barrier per chunk ----
    int sc = 0, sl = 2;
    for (int c = 0; c < NCHUNK; c++) {
        CP_WAIT(1);
        __syncthreads();
        if (c + 2 < NCHUNK) {
            const uint32_t sdst = sb + sl * STAGE_BYTES;
            const int cl = c + 2;
            if (useH && cl >= 16) {                 // h half from g_Ah1
                const size_t koff = (size_t)(cl - 16) * 128;
#pragma unroll
                for (int i = 0; i < 4; i++)
                    cp_async16(sdst + dA + i * 4096, Hbase + i * HSTRIDE + koff);
            } else {                                // input half / step-0 h2 from g_A
                const size_t koff = (size_t)cl * 128;
#pragma unroll
                for (int i = 0; i < 4; i++)
                    cp_async16(sdst + dA + i * 4096, Abase + i * ASTRIDE + koff);
            }
            const size_t koffB = (size_t)cl * 128;
#pragma unroll
            for (int j = 0; j < 5; j++)
                cp_async16(sdst + A_BYTES + dA + j * 4096, Bbase + j * BSTRIDE + koffB);
        }
        CP_COMMIT();

        const uint32_t sA = sb + sc * STAGE_BYTES;
#pragma unroll
        for (int kk = 0; kk < 4; kk++) {
            const uint32_t kb = kk * 32;
            const uint32_t bko = (kb + b_kh) ^ b_xor;   // folded once per kk
            uint32_t af[4][4];
#pragma unroll
            for (int mt = 0; mt < 4; mt++)
                LDSM4(af[mt][0], af[mt][1], af[mt][2], af[mt][3],
                      sA + a_rt[mt] + ((kb + a_kh) ^ a_xor[mt]));
            uint32_t bf[5][2];
#pragma unroll
            for (int gt = 0; gt < 5; gt++)
                LDSM2(bf[gt][0], bf[gt][1], sA + b_rt[gt] + bko);
#pragma unroll
            for (int mt = 0; mt < 4; mt++)
#pragma unroll
                for (int gt = 0; gt < 5; gt++)
                    MMA16816(acc[mt][gt], af[mt], bf[gt][0], bf[gt][1]);
        }

        sc = (sc == 2) ? 0 : sc + 1;
        sl = (sl == 2) ? 0 : sl + 1;
    }

    // ---- fused elementwise epilogue (all 5 gates resident in registers) ----
    const int trow = lane >> 2;
    const int tcol = (lane & 3) * 2;
    const int jb   = bj0 + wjj + tcol;             // global j for cc=0

    float bz[5][2];
#pragma unroll
    for (int gt = 0; gt < 5; gt++) {
        bz[gt][0] = __ldg(bias + gt * 1024 + jb);
        bz[gt][1] = __ldg(bias + gt * 1024 + jb + 1);
    }

    double lsum = 0.0;
#pragma unroll
    for (int mt = 0; mt < 4; mt++) {
#pragma unroll
        for (int r2 = 0; r2 < 2; r2++) {
            const int i = bm + wm + mt * 16 + trow + r2 * 8;
            const int* hrow = hidden + (size_t)i * 4096;
            const size_t ro = (size_t)i * 4096;
            const size_t oo = OUT_OH + (size_t)i * 2048 + (size_t)step * 1024;
#pragma unroll
            for (int cc = 0; cc < 2; cc++) {
                const int j = jb + cc;
                const int a = r2 * 2 + cc;
                const float xz = acc[mt][0][a] + bz[0][cc];
                const float xg = acc[mt][1][a] + bz[1][cc];
                const float xf = acc[mt][2][a] + bz[2][cc];
                const float xo = acc[mt][3][a] + bz[3][cc];
                const float xp = acc[mt][4][a] + bz[4][cc];

                const float z  = 0.96875f * sigm(xz) + 0.03125f;
                const float gg = tanhf(xg);
                const float f  = sigm(xf);
                const float o  = sigm(xo);
                const float p  = 0.96875f * sigm(xp) + 0.03125f;

                int zi = (int)(z * 1024.0f); if (zi < 1) zi = 1;
                int pi = (int)(p * 1024.0f); if (pi < 1) pi = 1;

                const int cv = hrow[(2 + step) * 1024 + j];
                const int hv = hrow[step * 1024 + j];

                const int cn = (int)(((long long)cv * (long long)zi) >> 10)
                             + (int)(f * gg * 8388608.0f);
                const float cfl = (float)cn * (1.0f / 8388608.0f);
                const int hn = (int)(((long long)hv * (long long)pi) >> 10)
                             + (int)(o * tanhf(cfl) * 8388608.0f);

                out[ro + (size_t)step * 1024 + j]       = (float)hn;
                out[ro + (size_t)(2 + step) * 1024 + j] = (float)cn;
                const float hfl = (float)hn * (1.0f / 8388608.0f);
                out[oo + j] = hfl;
                if (step == 0)
                    g_Ah1[(size_t)i * G_ + j] = __float2half_rn(hfl);

                lsum += (double)(logf(z) + logf(p));
            }
        }
    }

    // ---- deterministic per-CTA log reduction ----
    sred[tid] = lsum;
    __syncthreads();
#pragma unroll
    for (int s = 128; s > 0; s >>= 1) {
        if (tid < s) sred[tid] += sred[tid + s];
        __syncthreads();
    }
    if (tid == 0)
        g_part[step * 1024 + blockIdx.y * gridDim.x + blockIdx.x] = sred[0];
}

// ---------------------------------------------------------------------------
// Final scalar: optimal_bits = -(sum of logs) / ln2
// ---------------------------------------------------------------------------
__global__ void bits_kernel(float* __restrict__ out, long long last_idx)
{
    __shared__ double sred[256];
    const int tid = threadIdx.x;
    double s = 0.0;
    for (int i = tid; i < 2 * 1024; i += 256) s += g_part[i];
    sred[tid] = s;
    __syncthreads();
#pragma unroll
    for (int k = 128; k > 0; k >>= 1) {
        if (tid < k) sred[tid] += sred[tid + k];
        __syncthreads();
    }
    if (tid == 0)
        out[last_idx] = (float)(-sred[0] / 0.6931471805599453);
}

// ---------------------------------------------------------------------------
extern "C" void kernel_launch(void* const* d_in, const int* in_sizes, int n_in,
                              void* d_out, int out_size)
{
    const float* inp    = (const float*)d_in[0];   // (4096, 1024)
    const int*   hidden = (const int*)  d_in[1];   // (4096, 4096)
    const float* W1     = (const float*)d_in[2];   // (5120, 2048)
    const float* b1     = (const float*)d_in[3];
    const float* W2     = (const float*)d_in[4];
    const float* b2     = (const float*)d_in[5];
    float* out = (float*)d_out;

    static bool attr_set = false;
    if (!attr_set) {
        cudaFuncSetAttribute(gemm_fused_kernel,
                             cudaFuncAttributeMaxDynamicSharedMemorySize, SMEM_TOTAL);
        attr_set = true;
    }

    dim3 gemm_grid(G_ / 32, B_ / TMM);             // (32, 32)

    prep_kernel <<<(B_ * KD) / (256 * 8), 256>>>(inp, hidden);
    wconv_kernel<<<(2 * ND * KD) / (256 * 8), 256>>>(W1, W2);

    gemm_fused_kernel<<<gemm_grid, 256, SMEM_TOTAL>>>(0, b1, hidden, out);
    gemm_fused_kernel<<<gemm_grid, 256, SMEM_TOTAL>>>(1, b2, hidden, out);
    bits_kernel<<<1, 256>>>(out, (long long)out_size - 1);
}

// round 12
// speedup vs baseline: 1.4350x; 1.0641x over previous
#include <cuda_runtime.h>
#include <cuda_fp16.h>
#include <math.h>
#include <stdint.h>

// ---------------------------------------------------------------------------
// Problem constants
// ---------------------------------------------------------------------------
constexpr int B_  = 4096;    // batch
constexpr int G_  = 1024;    // gate width
constexpr int KD  = 2048;    // IN + g  (GEMM K)
constexpr int ND  = 5120;    // out_dim
constexpr long long OUT_OH = (long long)B_ * 4 * G_;

// ---------------------------------------------------------------------------
// Static scratch (no allocations allowed)
// ---------------------------------------------------------------------------
__device__ __align__(256) __half g_A  [(size_t)B_ * KD];   // [input | h2_fl] 16.8 MB
__device__ __align__(256) __half g_Ah1[(size_t)B_ * G_];   // h1_fl (step-1 h half) 8.4 MB
__device__ __align__(256) __half g_W1[(size_t)ND * KD];    // 21 MB
__device__ __align__(256) __half g_W2[(size_t)ND * KD];    // 21 MB
__device__ double g_part[2 * 1024];

// ---------------------------------------------------------------------------
// PTX helpers (all baseline sm_80+ features)
// ---------------------------------------------------------------------------
__device__ __forceinline__ uint32_t smem_u32(const void* p) {
    uint32_t a;
    asm("{ .reg .u64 t; cvta.to.shared.u64 t, %1; cvt.u32.u64 %0, t; }" : "=r"(a) : "l"(p));
    return a;
}
__device__ __forceinline__ void cp_async16(uint32_t dst, const void* src) {
    asm volatile("cp.async.cg.shared.global [%0], [%1], 16;" :: "r"(dst), "l"(src) : "memory");
}
#define CP_COMMIT()  asm volatile("cp.async.commit_group;" ::: "memory")
#define CP_WAIT(n)   asm volatile("cp.async.wait_group %0;" :: "n"(n) : "memory")

#define LDSM4(r0, r1, r2, r3, addr) \
    asm volatile("ldmatrix.sync.aligned.m8n8.x4.shared.b16 {%0,%1,%2,%3}, [%4];" \
                 : "=r"(r0), "=r"(r1), "=r"(r2), "=r"(r3) : "r"(addr))

#define LDSM2(r0, r1, addr) \
    asm volatile("ldmatrix.sync.aligned.m8n8.x2.shared.b16 {%0,%1}, [%2];" \
                 : "=r"(r0), "=r"(r1) : "r"(addr))

#define MMA16816(d, a, b0v, b1v) \
    asm volatile("mma.sync.aligned.m16n8k16.row.col.f32.f16.f16.f32 " \
                 "{%0,%1,%2,%3}, {%4,%5,%6,%7}, {%8,%9}, {%0,%1,%2,%3};" \
                 : "+f"((d)[0]), "+f"((d)[1]), "+f"((d)[2]), "+f"((d)[3]) \
                 : "r"((a)[0]), "r"((a)[1]), "r"((a)[2]), "r"((a)[3]), \
                   "r"(b0v), "r"(b1v))

#define SWZ(o) ((o) ^ (((o) >> 3) & 0x70))

// Fast transcendentals: ex2/rcp/lg2 approx (rel err ~1e-7; safe vs fp16 GEMM err)
__device__ __forceinline__ float fsigm(float x) {
    float e, r;
    asm("ex2.approx.f32 %0, %1;" : "=f"(e) : "f"(-1.4426950408889634f * x));
    asm("rcp.approx.f32 %0, %1;" : "=f"(r) : "f"(1.0f + e));
    return r;
}
__device__ __forceinline__ float ftanh(float x) {
    return fmaf(2.0f, fsigm(2.0f * x), -1.0f);
}
__device__ __forceinline__ float flog2(float x) {
    float r;
    asm("lg2.approx.f32 %0, %1;" : "=f"(r) : "f"(x));
    return r;
}

// ---------------------------------------------------------------------------
// Pack A = fp16([input | h2_fl]) — 8 elements per thread, 16B stores
// ---------------------------------------------------------------------------
__global__ void prep_kernel(const float* __restrict__ inp,
                            const int*   __restrict__ hidden)
{
    const int g = blockIdx.x * 256 + threadIdx.x;  // 0 .. B_*KD/8-1
    const int idx = g * 8;
    const int i = idx >> 11;
    const int k = idx & 2047;                      // multiple of 8; no boundary straddle
    __half h[8];
    if (k < 1024) {
        const float4 f0 = *(const float4*)(inp + (size_t)i * 1024 + k);
        const float4 f1 = *(const float4*)(inp + (size_t)i * 1024 + k + 4);
        h[0]=__float2half_rn(f0.x); h[1]=__float2half_rn(f0.y);
        h[2]=__float2half_rn(f0.z); h[3]=__float2half_rn(f0.w);
        h[4]=__float2half_rn(f1.x); h[5]=__float2half_rn(f1.y);
        h[6]=__float2half_rn(f1.z); h[7]=__float2half_rn(f1.w);
    } else {
        const int4 v0 = *(const int4*)(hidden + (size_t)i * 4096 + k);
        const int4 v1 = *(const int4*)(hidden + (size_t)i * 4096 + k + 4);
        const float s = 1.0f / 8388608.0f;
        h[0]=__float2half_rn((float)v0.x*s); h[1]=__float2half_rn((float)v0.y*s);
        h[2]=__float2half_rn((float)v0.z*s); h[3]=__float2half_rn((float)v0.w*s);
        h[4]=__float2half_rn((float)v1.x*s); h[5]=__float2half_rn((float)v1.y*s);
        h[6]=__float2half_rn((float)v1.z*s); h[7]=__float2half_rn((float)v1.w*s);
    }
    *(uint4*)(g_A + idx) = *(const uint4*)h;
}

// ---------------------------------------------------------------------------
// W1,W2 -> fp16, 8 elements per thread
// ---------------------------------------------------------------------------
__global__ void wconv_kernel(const float* __restrict__ W1src,
                             const float* __restrict__ W2src)
{
    constexpr size_t HALF = (size_t)ND * KD;
    const size_t idx = ((size_t)blockIdx.x * 256 + threadIdx.x) * 8;
    const float* src = (idx < HALF) ? (W1src + idx) : (W2src + (idx - HALF));
    __half* dst = (idx < HALF) ? (g_W1 + idx) : (g_W2 + (idx - HALF));
    const float4 f0 = *(const float4*)(src);
    const float4 f1 = *(const float4*)(src + 4);
    __half h[8];
    h[0]=__float2half_rn(f0.x); h[1]=__float2half_rn(f0.y);
    h[2]=__float2half_rn(f0.z); h[3]=__float2half_rn(f0.w);
    h[4]=__float2half_rn(f1.x); h[5]=__float2half_rn(f1.y);
    h[6]=__float2half_rn(f1.z); h[7]=__float2half_rn(f1.w);
    *(uint4*)dst = *(const uint4*)h;
}

// ---------------------------------------------------------------------------
// Fused GEMM + fixed-point half-step (R9/R11 GEMM core).
// CTA: M=128 batch rows x 32 j-columns x ALL 5 gates (B tile = 160 W rows).
// 8 warps: wm = (wid&1)*64, j-slice wjj = (wid>>1)*8.
// B: 5 gate blocks, one LDSM2 each per k16 slice.
// K-chunk 64, SW128 swizzle, 3-stage cp.async, one barrier per chunk.
// Step-1 h-half read from disjoint g_Ah1 (no cross-CTA WAR).
// Epilogue: full fixed-point update in registers with approx transcendentals.
// ---------------------------------------------------------------------------
constexpr int TMM = 128;
constexpr int A_BYTES = TMM * 128;                 // 16384 per stage
constexpr int B_BYTES = 160 * 128;                 // 20480 per stage
constexpr int STAGE_BYTES = A_BYTES + B_BYTES;     // 36864
constexpr int SMEM_TOTAL = 3 * STAGE_BYTES;        // 110592
constexpr int NCHUNK = KD / 64;                    // 32

__global__ __launch_bounds__(256, 2)
void gemm_fused_kernel(int step, const float* __restrict__ bias,
                       const int* __restrict__ hidden,
                       float* __restrict__ out)
{
    extern __shared__ char smem[];
    __shared__ double sred[256];
    const uint32_t sb = smem_u32(smem);
    const int tid  = threadIdx.x;
    const int wid  = tid >> 5;
    const int lane = tid & 31;
    const int bm  = blockIdx.y * TMM;
    const int bj0 = blockIdx.x * 32;
    const __half* __restrict__ Wg = step ? g_W2 : g_W1;

    // ---- producer setup: 4 A + 5 B cp.async per thread per stage ----
    const int prow = tid >> 3;                     // 0..31
    const int pgrp = tid & 7;                      // 0..7
    const char* Abase  = (const char*)(g_A   + (size_t)(bm + prow) * KD) + pgrp * 16;
    const char* Hbase  = (const char*)(g_Ah1 + (size_t)(bm + prow) * G_) + pgrp * 16;
    const char* Bbase  = (const char*)(Wg + (size_t)(bj0 + prow) * KD) + pgrp * 16;
    const uint32_t dA = SWZ((uint32_t)(prow * 128 + pgrp * 16));   // row step 32 is SWZ-safe
    constexpr size_t ASTRIDE = (size_t)32 * KD * 2;                // +32 rows in g_A
    constexpr size_t HSTRIDE = (size_t)32 * G_ * 2;                // +32 rows in g_Ah1
    constexpr size_t BSTRIDE = (size_t)1024 * KD * 2;              // next gate
    const bool useH = (step != 0);

    // ---- consumer setup ----
    const int wm  = (wid & 1) * 64;                // warp M offset
    const int wjj = (wid >> 1) * 8;                // warp j-slice
    const int q   = lane >> 3;                     // quad
    const int l7  = lane & 7;

    uint32_t a_rt[4], a_xor[4];
#pragma unroll
    for (int mt = 0; mt < 4; mt++) {
        const int row = wm + mt * 16 + l7 + (q & 1) * 8;
        a_rt[mt]  = (uint32_t)row * 128;
        a_xor[mt] = (uint32_t)(row & 7) * 16;
    }
    const uint32_t a_kh = (uint32_t)(q >> 1) * 16;

    // B: 5 gate blocks of 8 rows each; ldmatrix.x2 (lanes 0-15 give addresses)
    uint32_t b_rt[5];
#pragma unroll
    for (int gt = 0; gt < 5; gt++)
        b_rt[gt] = (uint32_t)(A_BYTES + (gt * 32 + wjj + l7) * 128);
    const uint32_t b_xor = (uint32_t)l7 * 16;
    const uint32_t b_kh  = (uint32_t)(q & 1) * 16;

    float acc[4][5][4];
#pragma unroll
    for (int mt = 0; mt < 4; mt++)
#pragma unroll
        for (int gt = 0; gt < 5; gt++)
#pragma unroll
            for (int r = 0; r < 4; r++) acc[mt][gt][r] = 0.0f;

    // ---- prologue: chunks 0,1 into stages 0,1 (low chunks -> g_A) ----
#pragma unroll
    for (int s = 0; s < 2; s++) {
        const uint32_t sdst = sb + s * STAGE_BYTES;
        const size_t koff = (size_t)s * 128;
#pragma unroll
        for (int i = 0; i < 4; i++)
            cp_async16(sdst + dA + i * 4096, Abase + i * ASTRIDE + koff);
#pragma unroll
        for (int j = 0; j < 5; j++)
            cp_async16(sdst + A_BYTES + dA + j * 4096, Bbase + j * BSTRIDE + koff);
        CP_COMMIT();
    }

    // ---- main loop: one barrier per chunk ----
    int sc = 0, sl = 2;
    for (int c = 0; c < NCHUNK; c++) {
        CP_WAIT(1);
        __syncthreads();
        if (c + 2 < NCHUNK) {
            const uint32_t sdst = sb + sl * STAGE_BYTES;
            const int cl = c + 2;
            if (useH && cl >= 16) {                 // h half from g_Ah1
                const size_t koff = (size_t)(cl - 16) * 128;
#pragma unroll
                for (int i = 0; i < 4; i++)
                    cp_async16(sdst + dA + i * 4096, Hbase + i * HSTRIDE + koff);
            } else {                                // input half / step-0 h2 from g_A
                const size_t koff = (size_t)cl * 128;
#pragma unroll
                for (int i = 0; i < 4; i++)
                    cp_async16(sdst + dA + i * 4096, Abase + i * ASTRIDE + koff);
            }
            const size_t koffB = (size_t)cl * 128;
#pragma unroll
            for (int j = 0; j < 5; j++)
                cp_async16(sdst + A_BYTES + dA + j * 4096, Bbase + j * BSTRIDE + koffB);
        }
        CP_COMMIT();

        const uint32_t sA = sb + sc * STAGE_BYTES;
#pragma unroll
        for (int kk = 0; kk < 4; kk++) {
            const uint32_t kb = kk * 32;
            const uint32_t bko = (kb + b_kh) ^ b_xor;   // folded once per kk
            uint32_t af[4][4];
#pragma unroll
            for (int mt = 0; mt < 4; mt++)
                LDSM4(af[mt][0], af[mt][1], af[mt][2], af[mt][3],
                      sA + a_rt[mt] + ((kb + a_kh) ^ a_xor[mt]));
            uint32_t bf[5][2];
#pragma unroll
            for (int gt = 0; gt < 5; gt++)
                LDSM2(bf[gt][0], bf[gt][1], sA + b_rt[gt] + bko);
#pragma unroll
            for (int mt = 0; mt < 4; mt++)
#pragma unroll
                for (int gt = 0; gt < 5; gt++)
                    MMA16816(acc[mt][gt], af[mt], bf[gt][0], bf[gt][1]);
        }

        sc = (sc == 2) ? 0 : sc + 1;
        sl = (sl == 2) ? 0 : sl + 1;
    }

    // ---- fused elementwise epilogue (all 5 gates resident in registers) ----
    const int trow = lane >> 2;
    const int tcol = (lane & 3) * 2;
    const int jb   = bj0 + wjj + tcol;             // global j for cc=0

    float bz[5][2];
#pragma unroll
    for (int gt = 0; gt < 5; gt++) {
        bz[gt][0] = __ldg(bias + gt * 1024 + jb);
        bz[gt][1] = __ldg(bias + gt * 1024 + jb + 1);
    }

    double lsum = 0.0;
#pragma unroll
    for (int mt = 0; mt < 4; mt++) {
#pragma unroll
        for (int r2 = 0; r2 < 2; r2++) {
            const int i = bm + wm + mt * 16 + trow + r2 * 8;
            const int* hrow = hidden + (size_t)i * 4096;
            const size_t ro = (size_t)i * 4096;
            const size_t oo = OUT_OH + (size_t)i * 2048 + (size_t)step * 1024;
#pragma unroll
            for (int cc = 0; cc < 2; cc++) {
                const int j = jb + cc;
                const int a = r2 * 2 + cc;
                const float xz = acc[mt][0][a] + bz[0][cc];
                const float xg = acc[mt][1][a] + bz[1][cc];
                const float xf = acc[mt][2][a] + bz[2][cc];
                const float xo = acc[mt][3][a] + bz[3][cc];
                const float xp = acc[mt][4][a] + bz[4][cc];

                const float z  = 0.96875f * fsigm(xz) + 0.03125f;
                const float gg = ftanh(xg);
                const float f  = fsigm(xf);
                const float o  = fsigm(xo);
                const float p  = 0.96875f * fsigm(xp) + 0.03125f;

                int zi = (int)(z * 1024.0f); if (zi < 1) zi = 1;
                int pi = (int)(p * 1024.0f); if (pi < 1) pi = 1;

                const int cv = hrow[(2 + step) * 1024 + j];
                const int hv = hrow[step * 1024 + j];

                const int cn = (int)(((long long)cv * (long long)zi) >> 10)
                             + (int)(f * gg * 8388608.0f);
                const float cfl = (float)cn * (1.0f / 8388608.0f);
                const int hn = (int)(((long long)hv * (long long)pi) >> 10)
                             + (int)(o * ftanh(cfl) * 8388608.0f);

                out[ro + (size_t)step * 1024 + j]       = (float)hn;
                out[ro + (size_t)(2 + step) * 1024 + j] = (float)cn;
                const float hfl = (float)hn * (1.0f / 8388608.0f);
                out[oo + j] = hfl;
                if (step == 0)
                    g_Ah1[(size_t)i * G_ + j] = __float2half_rn(hfl);

                lsum += (double)flog2(z * p);      // sum of log2 directly
            }
        }
    }

    // ---- deterministic per-CTA log2 reduction ----
    sred[tid] = lsum;
    __syncthreads();
#pragma unroll
    for (int s = 128; s > 0; s >>= 1) {
        if (tid < s) sred[tid] += sred[tid + s];
        __syncthreads();
    }
    if (tid == 0)
        g_part[step * 1024 + blockIdx.y * gridDim.x + blockIdx.x] = sred[0];
}

// ---------------------------------------------------------------------------
// Final scalar: optimal_bits = -(sum of log2)
// ---------------------------------------------------------------------------
__global__ void bits_kernel(float* __restrict__ out, long long last_idx)
{
    __shared__ double sred[256];
    const int tid = threadIdx.x;
    double s = 0.0;
    for (int i = tid; i < 2 * 1024; i += 256) s += g_part[i];
    sred[tid] = s;
    __syncthreads();
#pragma unroll
    for (int k = 128; k > 0; k >>= 1) {
        if (tid < k) sred[tid] += sred[tid + k];
        __syncthreads();
    }
    if (tid == 0)
        out[last_idx] = (float)(-sred[0]);
}

// ---------------------------------------------------------------------------
extern "C" void kernel_launch(void* const* d_in, const int* in_sizes, int n_in,
                              void* d_out, int out_size)
{
    const float* inp    = (const float*)d_in[0];   // (4096, 1024)
    const int*   hidden = (const int*)  d_in[1];   // (4096, 4096)
    const float* W1     = (const float*)d_in[2];   // (5120, 2048)
    const float* b1     = (const float*)d_in[3];
    const float* W2     = (const float*)d_in[4];
    const float* b2     = (const float*)d_in[5];
    float* out = (float*)d_out;

    static bool attr_set = false;
    if (!attr_set) {
        cudaFuncSetAttribute(gemm_fused_kernel,
                             cudaFuncAttributeMaxDynamicSharedMemorySize, SMEM_TOTAL);
        attr_set = true;
    }

    dim3 gemm_grid(G_ / 32, B_ / TMM);             // (32, 32)

    prep_kernel <<<(B_ * KD) / (256 * 8), 256>>>(inp, hidden);
    wconv_kernel<<<(2 * ND * KD) / (256 * 8), 256>>>(W1, W2);

    gemm_fused_kernel<<<gemm_grid, 256, SMEM_TOTAL>>>(0, b1, hidden, out);
    gemm_fused_kernel<<<gemm_grid, 256, SMEM_TOTAL>>>(1, b2, hidden, out);
    bits_kernel<<<1, 256>>>(out, (long long)out_size - 1);
}